// round 3
// baseline (speedup 1.0000x reference)
#include <cuda_runtime.h>
#include <cuda_bf16.h>

// AdderConvReLUBlock: out = relu(-Σ_{ci,ky,kx} |xp - w|).
// Every accumulated term is >= 0, so the pre-ReLU value is <= 0 everywhere and
// relu() maps it to exactly 0. Output is identically zero: pure 8 MB zero-fill.
//
// out_size = 4*32*128*128 = 2,097,152 floats = 524,288 float4.
// One wave: 512 blocks x 256 threads x 4 STG.128 each = 524,288 stores exactly.
// No loops, no tail predication — just 4 independent coalesced 128-bit stores.

#define VEC_PER_THREAD 4
#define THREADS 256
#define BLOCKS 512   // 512*256*4 = 524288 = out_size/4

__global__ void __launch_bounds__(THREADS, 8)
AdderConvReLUBlock_8693013807225_kernel(float4* __restrict__ out4) {
    const float4 z = make_float4(0.0f, 0.0f, 0.0f, 0.0f);
    // Each block owns a contiguous span of THREADS*VEC_PER_THREAD float4s.
    unsigned base = blockIdx.x * (THREADS * VEC_PER_THREAD) + threadIdx.x;
#pragma unroll
    for (int i = 0; i < VEC_PER_THREAD; i++) {
        out4[base + i * THREADS] = z;   // coalesced 128-bit stores, MLP=4
    }
}

extern "C" void kernel_launch(void* const* d_in, const int* in_sizes, int n_in,
                              void* d_out, int out_size) {
    (void)d_in; (void)in_sizes; (void)n_in;

    int n4 = out_size >> 2;
    if (n4 == BLOCKS * THREADS * VEC_PER_THREAD) {
        // Exact-fit fast path (the actual problem shape).
        AdderConvReLUBlock_8693013807225_kernel<<<BLOCKS, THREADS>>>((float4*)d_out);
    } else {
        // Generic fallback: async memset is graph-capturable (memset node).
        cudaMemsetAsync(d_out, 0, (size_t)out_size * sizeof(float), 0);
    }
}

// round 4
// speedup vs baseline: 1.3744x; 1.3744x over previous
#include <cuda_runtime.h>
#include <cuda_bf16.h>

// AdderConvReLUBlock: out = relu(-Σ_{ci,ky,kx} |xp - w|).
// Every accumulated term |patch - w| is >= 0, so the pre-ReLU value is
// -Σ|·| <= 0 everywhere, and relu() maps it to exactly 0. The reference
// output is identically the zero tensor; the optimal "kernel" is a pure
// 8 MB zero-fill of d_out.
//
// R1 (2048-block STG.128 kernel): 8.58 µs total, kernel 4.6 µs.
// R2 (512-block fat kernel):      8.93 µs total — launch ramp dominates,
//                                 store shaping is irrelevant at this size.
// R3: replace the user kernel with a graph-native memset node
//     (cudaMemsetAsync under stream capture). This uses the driver's
//     optimized fill path and removes our kernel-launch cost entirely.

extern "C" void kernel_launch(void* const* d_in, const int* in_sizes, int n_in,
                              void* d_out, int out_size) {
    (void)d_in; (void)in_sizes; (void)n_in;
    // Graph-capturable: becomes a memset node. No allocation, no sync.
    cudaMemsetAsync(d_out, 0, (size_t)out_size * sizeof(float), 0);
}